// round 1
// baseline (speedup 1.0000x reference)
#include <cuda_runtime.h>
#include <math.h>

// Problem constants (fixed by the reference: B=4, S=2048, D=1024)
#define BB   4
#define SSQ  2048
#define DDIM 1024
#define CHN  128               // chunk length
#define NCH  (SSQ/CHN)         // 16 chunks
#define EPSV 1e-6f

// ---------------- scratch (device globals; no cudaMalloc allowed) ----------
__device__ float g_q[BB*SSQ*DDIM];          // relu(x Wq^T + bq)      32 MB
__device__ float g_k[BB*SSQ*DDIM];          // relu(x Wk^T + bk)      32 MB
__device__ float g_v[BB*SSQ*DDIM];          //      x Wv^T + bv       32 MB
__device__ float g_A[BB*NCH*CHN*CHN];       // per-chunk Q K^T (later masked in place)  4 MB
__device__ float g_den[BB*SSQ];             // denominators
__device__ float g_zb[NCH*BB*DDIM];         // z state at each chunk start
__device__ float g_zp[NCH*BB*DDIM];         // per-chunk z partials
__device__ float g_St[BB*DDIM*DDIM];        // S state [B,D,D]        16 MB

// ---------------------------------------------------------------------------
// zero the S state (it persists across graph replays -> must re-zero per call)
__global__ void zeroS_kernel()
{
    size_t i = (size_t)blockIdx.x * blockDim.x + threadIdx.x;   // float4 index
    ((float4*)g_St)[i] = make_float4(0.f, 0.f, 0.f, 0.f);
}

// ---------------------------------------------------------------------------
// Projections: out[m,n] = act( sum_d x[m,d] * W[n,d] + b[n] )
// M = B*S = 8192, N = D, K = D.  Tile 128x128x8, 256 threads, 8x8 per thread.
__global__ __launch_bounds__(256) void proj_kernel(
    const float* __restrict__ x,
    const float* __restrict__ Wq, const float* __restrict__ bq,
    const float* __restrict__ Wk, const float* __restrict__ bk,
    const float* __restrict__ Wv, const float* __restrict__ bv)
{
    const int which = blockIdx.z;
    const float* W    = (which == 0) ? Wq : (which == 1) ? Wk : Wv;
    const float* bias = (which == 0) ? bq : (which == 1) ? bk : bv;
    float* outp       = (which == 0) ? g_q : (which == 1) ? g_k : g_v;
    const bool do_relu = (which < 2);

    __shared__ float As[8][128];
    __shared__ float Bs[8][128];

    const int tid = threadIdx.x;
    const int tx = tid & 15, ty = tid >> 4;
    const int m0 = blockIdx.y * 128;
    const int n0 = blockIdx.x * 128;
    const int lr = tid >> 1;          // 0..127
    const int lc = (tid & 1) * 4;     // 0 or 4

    const float* Aptr = x + (size_t)(m0 + lr) * DDIM + lc;
    const float* Bptr = W + (size_t)(n0 + lr) * DDIM + lc;

    float acc[8][8];
#pragma unroll
    for (int i = 0; i < 8; i++)
#pragma unroll
        for (int j = 0; j < 8; j++) acc[i][j] = 0.f;

    for (int k0 = 0; k0 < DDIM; k0 += 8) {
        float4 a4 = *(const float4*)(Aptr + k0);
        float4 b4 = *(const float4*)(Bptr + k0);
        __syncthreads();
        As[lc + 0][lr] = a4.x; As[lc + 1][lr] = a4.y;
        As[lc + 2][lr] = a4.z; As[lc + 3][lr] = a4.w;
        Bs[lc + 0][lr] = b4.x; Bs[lc + 1][lr] = b4.y;
        Bs[lc + 2][lr] = b4.z; Bs[lc + 3][lr] = b4.w;
        __syncthreads();
#pragma unroll
        for (int kk = 0; kk < 8; kk++) {
            float4 a0 = *(const float4*)&As[kk][ty * 8];
            float4 a1 = *(const float4*)&As[kk][ty * 8 + 4];
            float4 b0 = *(const float4*)&Bs[kk][tx * 8];
            float4 b1 = *(const float4*)&Bs[kk][tx * 8 + 4];
            float ar_[8] = {a0.x, a0.y, a0.z, a0.w, a1.x, a1.y, a1.z, a1.w};
            float br_[8] = {b0.x, b0.y, b0.z, b0.w, b1.x, b1.y, b1.z, b1.w};
#pragma unroll
            for (int i = 0; i < 8; i++)
#pragma unroll
                for (int j = 0; j < 8; j++)
                    acc[i][j] = fmaf(ar_[i], br_[j], acc[i][j]);
        }
    }

    float bv8[8];
#pragma unroll
    for (int j = 0; j < 8; j++) bv8[j] = bias[n0 + tx * 8 + j];

#pragma unroll
    for (int i = 0; i < 8; i++) {
        const size_t row = (size_t)(m0 + ty * 8 + i);
#pragma unroll
        for (int j0 = 0; j0 < 8; j0 += 4) {
            float4 r;
            r.x = acc[i][j0 + 0] + bv8[j0 + 0];
            r.y = acc[i][j0 + 1] + bv8[j0 + 1];
            r.z = acc[i][j0 + 2] + bv8[j0 + 2];
            r.w = acc[i][j0 + 3] + bv8[j0 + 3];
            if (do_relu) {
                r.x = fmaxf(r.x, 0.f); r.y = fmaxf(r.y, 0.f);
                r.z = fmaxf(r.z, 0.f); r.w = fmaxf(r.w, 0.f);
            }
            *(float4*)&outp[row * DDIM + n0 + tx * 8 + j0] = r;
        }
    }
}

// ---------------------------------------------------------------------------
// Per-chunk A = Q_chunk @ K_chunk^T  (128x128, K = D).  One CTA per (b,chunk).
__global__ __launch_bounds__(256) void qk_kernel()
{
    const int bid = blockIdx.x;          // 0..63
    const int b = bid / NCH, ch = bid % NCH;
    const float* qp = g_q + ((size_t)b * SSQ + (size_t)ch * CHN) * DDIM;
    const float* kp = g_k + ((size_t)b * SSQ + (size_t)ch * CHN) * DDIM;
    float* outp = g_A + (size_t)bid * CHN * CHN;

    __shared__ float As[8][128];
    __shared__ float Bs[8][128];

    const int tid = threadIdx.x;
    const int tx = tid & 15, ty = tid >> 4;
    const int lr = tid >> 1;
    const int lc = (tid & 1) * 4;

    const float* Aptr = qp + (size_t)lr * DDIM + lc;
    const float* Bptr = kp + (size_t)lr * DDIM + lc;

    float acc[8][8];
#pragma unroll
    for (int i = 0; i < 8; i++)
#pragma unroll
        for (int j = 0; j < 8; j++) acc[i][j] = 0.f;

    for (int k0 = 0; k0 < DDIM; k0 += 8) {
        float4 a4 = *(const float4*)(Aptr + k0);
        float4 b4 = *(const float4*)(Bptr + k0);
        __syncthreads();
        As[lc + 0][lr] = a4.x; As[lc + 1][lr] = a4.y;
        As[lc + 2][lr] = a4.z; As[lc + 3][lr] = a4.w;
        Bs[lc + 0][lr] = b4.x; Bs[lc + 1][lr] = b4.y;
        Bs[lc + 2][lr] = b4.z; Bs[lc + 3][lr] = b4.w;
        __syncthreads();
#pragma unroll
        for (int kk = 0; kk < 8; kk++) {
            float4 a0 = *(const float4*)&As[kk][ty * 8];
            float4 a1 = *(const float4*)&As[kk][ty * 8 + 4];
            float4 b0 = *(const float4*)&Bs[kk][tx * 8];
            float4 b1 = *(const float4*)&Bs[kk][tx * 8 + 4];
            float ar_[8] = {a0.x, a0.y, a0.z, a0.w, a1.x, a1.y, a1.z, a1.w};
            float br_[8] = {b0.x, b0.y, b0.z, b0.w, b1.x, b1.y, b1.z, b1.w};
#pragma unroll
            for (int i = 0; i < 8; i++)
#pragma unroll
                for (int j = 0; j < 8; j++)
                    acc[i][j] = fmaf(ar_[i], br_[j], acc[i][j]);
        }
    }

#pragma unroll
    for (int i = 0; i < 8; i++)
#pragma unroll
        for (int j0 = 0; j0 < 8; j0 += 4) {
            float4 r;
            r.x = acc[i][j0 + 0]; r.y = acc[i][j0 + 1];
            r.z = acc[i][j0 + 2]; r.w = acc[i][j0 + 3];
            *(float4*)&outp[(size_t)(ty * 8 + i) * CHN + tx * 8 + j0] = r;
        }
}

// ---------------------------------------------------------------------------
// z partials per chunk: zp[ch,b,d] = sum_{j<C} gamma^{C-1-j} k[b, ch*C+j, d]
__global__ void zpart_kernel(const float* __restrict__ gamma_ptr)
{
    const int idx = blockIdx.x * 256 + threadIdx.x;   // < NCH*B*D
    const float g = *gamma_ptr;
    const int ch = idx / (BB * DDIM);
    const int r  = idx % (BB * DDIM);
    const int b = r / DDIM, d = r % DDIM;
    const float* kp = g_k + ((size_t)b * SSQ + (size_t)ch * CHN) * DDIM + d;
    float acc = 0.f;
    for (int j = 0; j < CHN; j++) acc = fmaf(g, acc, kp[(size_t)j * DDIM]);
    g_zp[idx] = acc;
}

// z at chunk starts: zb[0]=0; zb[ch+1] = gamma^C * zb[ch] + zp[ch]
__global__ void zcomb_kernel(const float* __restrict__ gamma_ptr)
{
    const int r = blockIdx.x * 256 + threadIdx.x;    // < B*D
    const float g  = *gamma_ptr;
    const float gC = powf(g, (float)CHN);
    float run = 0.f;
    for (int ch = 0; ch < NCH; ch++) {
        g_zb[(size_t)ch * BB * DDIM + r] = run;
        run = fmaf(gC, run, g_zp[(size_t)ch * BB * DDIM + r]);
    }
}

// ---------------------------------------------------------------------------
// Apply decay mask to A in place + compute denominators.
// One warp per row (b, ch, i).
__global__ __launch_bounds__(256) void maskden_kernel(const float* __restrict__ gamma_ptr)
{
    __shared__ float gpow[CHN + 1];
    const float g = *gamma_ptr;
    const int tid = threadIdx.x;
    if (tid <= CHN) gpow[tid] = powf(g, (float)tid);
    __syncthreads();

    const int warp = tid >> 5, lane = tid & 31;
    const int rid = blockIdx.x * 8 + warp;           // < B*NCH*CHN = 8192
    const int b   = rid / (NCH * CHN);
    const int rem = rid % (NCH * CHN);
    const int ch = rem / CHN, i = rem % CHN;
    const int t = ch * CHN + i;

    float* Arow = g_A + (size_t)rid * CHN;           // rid == ((b*NCH+ch)*CHN + i)
    float rs = 0.f;
    for (int j = lane; j < CHN; j += 32) {
        float v = Arow[j];
        v = (j <= i) ? v * gpow[i - j] : 0.f;
        Arow[j] = v;
        rs += v;
    }
#pragma unroll
    for (int o = 16; o; o >>= 1) rs += __shfl_xor_sync(0xffffffffu, rs, o);

    const float* qrow = g_q + ((size_t)b * SSQ + t) * DDIM;
    const float* zb   = g_zb + ((size_t)ch * BB + b) * DDIM;
    float qz = 0.f;
    for (int d = lane; d < DDIM; d += 32) qz = fmaf(qrow[d], zb[d], qz);
#pragma unroll
    for (int o = 16; o; o >>= 1) qz += __shfl_xor_sync(0xffffffffu, qz, o);

    if (lane == 0)
        g_den[(size_t)b * SSQ + t] = gpow[i + 1] * qz + rs + EPSV;
}

// ---------------------------------------------------------------------------
// Per-chunk output: out[b, c0+i, n] =
//   ( gamma^{i+1} * (q_i @ S_prev)[n] + (Am[i,:] @ V_chunk)[n] ) / den[b,c0+i]
// Tile 64x64, 256 threads, 4x4/thread, BK=16. Grid (D/64, C/64, B) = 128 CTAs.
__global__ __launch_bounds__(256) void out_kernel(
    const float* __restrict__ gamma_ptr, int ch, float* __restrict__ outp)
{
    __shared__ float As[16][68];
    __shared__ float Bs[16][68];

    const float g = *gamma_ptr;
    const int b  = blockIdx.z;
    const int m0 = blockIdx.y * 64;
    const int n0 = blockIdx.x * 64;
    const int c0 = ch * CHN;
    const int tid = threadIdx.x;
    const int tx = tid & 15, ty = tid >> 4;
    const int ar = tid >> 2;          // 0..63  (A loader: NK layout)
    const int ac = (tid & 3) * 4;     // 0,4,8,12
    const int bk = tid >> 4;          // 0..15  (B loader: KN layout)
    const int bn = (tid & 15) * 4;    // 0..60

    float acc[4][4];
#pragma unroll
    for (int i = 0; i < 4; i++)
#pragma unroll
        for (int j = 0; j < 4; j++) acc[i][j] = 0.f;

    // ---- phase 1: (gamma^{i+1} q_i) @ S_prev, K = D ----
    const float rowscale = powf(g, (float)(m0 + ar + 1));
    const float* qp = g_q + ((size_t)b * SSQ + c0 + m0 + ar) * DDIM + ac;
    const float* Sp = g_St + (size_t)b * DDIM * DDIM;

    for (int k0 = 0; k0 < DDIM; k0 += 16) {
        float4 a4 = *(const float4*)(qp + k0);
        float4 b4 = *(const float4*)(Sp + (size_t)(k0 + bk) * DDIM + n0 + bn);
        __syncthreads();
        As[ac + 0][ar] = a4.x * rowscale; As[ac + 1][ar] = a4.y * rowscale;
        As[ac + 2][ar] = a4.z * rowscale; As[ac + 3][ar] = a4.w * rowscale;
        *(float4*)&Bs[bk][bn] = b4;
        __syncthreads();
#pragma unroll
        for (int kk = 0; kk < 16; kk++) {
            float4 av = *(const float4*)&As[kk][ty * 4];
            float4 bv = *(const float4*)&Bs[kk][tx * 4];
            float ar_[4] = {av.x, av.y, av.z, av.w};
            float br_[4] = {bv.x, bv.y, bv.z, bv.w};
#pragma unroll
            for (int i = 0; i < 4; i++)
#pragma unroll
                for (int j = 0; j < 4; j++)
                    acc[i][j] = fmaf(ar_[i], br_[j], acc[i][j]);
        }
    }

    // ---- phase 2: Am @ V_chunk, K = C ----
    const float* Ap = g_A + ((size_t)(b * NCH + ch) * CHN + m0 + ar) * CHN + ac;
    const float* Vp = g_v + ((size_t)b * SSQ + c0) * DDIM;

    for (int k0 = 0; k0 < CHN; k0 += 16) {
        float4 a4 = *(const float4*)(Ap + k0);
        float4 b4 = *(const float4*)(Vp + (size_t)(k0 + bk) * DDIM + n0 + bn);
        __syncthreads();
        As[ac + 0][ar] = a4.x; As[ac + 1][ar] = a4.y;
        As[ac + 2][ar] = a4.z; As[ac + 3][ar] = a4.w;
        *(float4*)&Bs[bk][bn] = b4;
        __syncthreads();
#pragma unroll
        for (int kk = 0; kk < 16; kk++) {
            float4 av = *(const float4*)&As[kk][ty * 4];
            float4 bv = *(const float4*)&Bs[kk][tx * 4];
            float ar_[4] = {av.x, av.y, av.z, av.w};
            float br_[4] = {bv.x, bv.y, bv.z, bv.w};
#pragma unroll
            for (int i = 0; i < 4; i++)
#pragma unroll
                for (int j = 0; j < 4; j++)
                    acc[i][j] = fmaf(ar_[i], br_[j], acc[i][j]);
        }
    }

#pragma unroll
    for (int ii = 0; ii < 4; ii++) {
        const int i = m0 + ty * 4 + ii;
        const int t = c0 + i;
        const float inv = 1.f / g_den[(size_t)b * SSQ + t];
        float4 r;
        r.x = acc[ii][0] * inv; r.y = acc[ii][1] * inv;
        r.z = acc[ii][2] * inv; r.w = acc[ii][3] * inv;
        *(float4*)&outp[((size_t)b * SSQ + t) * DDIM + n0 + tx * 4] = r;
    }
}

// ---------------------------------------------------------------------------
// Per-chunk state update: S[b] = gamma^C * S[b] + sum_tau gamma^{C-1-tau} k_tau v_tau^T
// Tile 64x64, K = C = 128. Grid (16,16,B) = 1024 CTAs. In-place RMW (own tile only).
__global__ __launch_bounds__(256) void update_kernel(const float* __restrict__ gamma_ptr, int ch)
{
    __shared__ float As[16][68];
    __shared__ float Bs[16][68];

    const float g  = *gamma_ptr;
    const float gC = powf(g, (float)CHN);
    const int b  = blockIdx.z;
    const int m0 = blockIdx.y * 64;
    const int n0 = blockIdx.x * 64;
    const int c0 = ch * CHN;
    const int tid = threadIdx.x;
    const int tx = tid & 15, ty = tid >> 4;
    const int lk = tid >> 4;          // 0..15 (tau within K-tile)
    const int ln = (tid & 15) * 4;    // column within 64

    const float* kp = g_k + ((size_t)b * SSQ + c0) * DDIM;
    const float* vp = g_v + ((size_t)b * SSQ + c0) * DDIM;

    float acc[4][4];
#pragma unroll
    for (int i = 0; i < 4; i++)
#pragma unroll
        for (int j = 0; j < 4; j++) acc[i][j] = 0.f;

    for (int k0 = 0; k0 < CHN; k0 += 16) {
        const float w = powf(g, (float)(CHN - 1 - (k0 + lk)));
        float4 a4 = *(const float4*)(kp + (size_t)(k0 + lk) * DDIM + m0 + ln);
        float4 b4 = *(const float4*)(vp + (size_t)(k0 + lk) * DDIM + n0 + ln);
        __syncthreads();
        As[lk][ln + 0] = a4.x * w; As[lk][ln + 1] = a4.y * w;
        As[lk][ln + 2] = a4.z * w; As[lk][ln + 3] = a4.w * w;
        *(float4*)&Bs[lk][ln] = b4;
        __syncthreads();
#pragma unroll
        for (int kk = 0; kk < 16; kk++) {
            float4 av = *(const float4*)&As[kk][ty * 4];
            float4 bv = *(const float4*)&Bs[kk][tx * 4];
            float ar_[4] = {av.x, av.y, av.z, av.w};
            float br_[4] = {bv.x, bv.y, bv.z, bv.w};
#pragma unroll
            for (int i = 0; i < 4; i++)
#pragma unroll
                for (int j = 0; j < 4; j++)
                    acc[i][j] = fmaf(ar_[i], br_[j], acc[i][j]);
        }
    }

    float* Sp = g_St + (size_t)b * DDIM * DDIM;
#pragma unroll
    for (int ii = 0; ii < 4; ii++) {
        const size_t row = (size_t)(m0 + ty * 4 + ii);
        float4 old = *(const float4*)&Sp[row * DDIM + n0 + tx * 4];
        float4 r;
        r.x = fmaf(gC, old.x, acc[ii][0]);
        r.y = fmaf(gC, old.y, acc[ii][1]);
        r.z = fmaf(gC, old.z, acc[ii][2]);
        r.w = fmaf(gC, old.w, acc[ii][3]);
        *(float4*)&Sp[row * DDIM + n0 + tx * 4] = r;
    }
}

// ---------------------------------------------------------------------------
extern "C" void kernel_launch(void* const* d_in, const int* in_sizes, int n_in,
                              void* d_out, int out_size)
{
    (void)in_sizes; (void)n_in; (void)out_size;
    const float* x  = (const float*)d_in[0];
    const float* Wq = (const float*)d_in[1];
    const float* bq = (const float*)d_in[2];
    const float* Wk = (const float*)d_in[3];
    const float* bk = (const float*)d_in[4];
    const float* Wv = (const float*)d_in[5];
    const float* bv = (const float*)d_in[6];
    const float* gp = (const float*)d_in[7];
    float* outp = (float*)d_out;

    // 1. re-zero the S state (device global persists across graph replays)
    zeroS_kernel<<<(BB * DDIM * DDIM / 4) / 256, 256>>>();

    // 2. projections q, k, v
    dim3 pg(DDIM / 128, (BB * SSQ) / 128, 3);
    proj_kernel<<<pg, 256>>>(x, Wq, bq, Wk, bk, Wv, bv);

    // 3. all per-chunk Q K^T matrices (state-independent)
    qk_kernel<<<BB * NCH, 256>>>();

    // 4. z boundary states
    zpart_kernel<<<(NCH * BB * DDIM) / 256, 256>>>(gp);
    zcomb_kernel<<<(BB * DDIM) / 256, 256>>>(gp);

    // 5. decay mask + denominators (in-place on g_A)
    maskden_kernel<<<(BB * NCH * CHN) / 8, 256>>>(gp);

    // 6. sequential chunk loop: output then state update (stream-serialized)
    for (int ch = 0; ch < NCH; ch++) {
        out_kernel<<<dim3(DDIM / 64, CHN / 64, BB), 256>>>(gp, ch, outp);
        update_kernel<<<dim3(DDIM / 64, DDIM / 64, BB), 256>>>(gp, ch);
    }
}